// round 7
// baseline (speedup 1.0000x reference)
#include <cuda_runtime.h>
#include <cuda_bf16.h>

// Causal BoW = running mean along T. Shapes: B=32, T=2048, C=512, fp32.
//
// Single-pass CHAINED scan, SELF-CLEANING (no clear kernel):
//  tile = (chain, tk): chain = (b, c-half) -> 64 chains; tk = chunk of
//  R=16 rows -> 128 chunks/chain; 8192 tiles.
//  256-thread CTA = one thread per column, 16 rows in registers.
//  6 CTAs/SM (launch_bounds) -> ~75% occupancy: more independent tiles in
//  flight to overlap load-latency / spin / store phases across CTAs.
//  Per-column inclusive prefixes published as ONE packed 64-bit word
//  (status<<32 | float bits) via atomicExch. Successor threads spin with
//  volatile 64-bit loads, then RESET the slot (consume-and-reset). Last
//  chunk never publishes; final ticket-holder resets the ticket. All
//  device state returns to zero after every launch: graph-safe, no allocs.

#define B_DIM 32
#define T_DIM 2048
#define C_DIM 512
#define R_ROWS 16
#define CGROUP 256
#define NCHAINS (B_DIM * (C_DIM / CGROUP))   // 64
#define NTK (T_DIM / R_ROWS)                 // 128
#define NTILES (NCHAINS * NTK)               // 8192

__device__ unsigned long long g_incl[(size_t)NTILES * CGROUP];  // 16 MB packed
__device__ unsigned int g_ticket;

__global__ __launch_bounds__(CGROUP, 6)
void causal_bow_scan(const float* __restrict__ x, float* __restrict__ out) {
    __shared__ unsigned s_tile;
    __shared__ float s_inv[R_ROWS];

    const int tid = threadIdx.x;
    if (tid == 0) {
        unsigned t = atomicAdd(&g_ticket, 1u);
        s_tile = t;
        // Last ticket drawn -> all atomicAdds on g_ticket have serialized;
        // safe to reset for the next (graph-replayed) launch.
        if (t == NTILES - 1) atomicExch(&g_ticket, 0u);
    }
    __syncthreads();

    const unsigned vt = s_tile;
    const unsigned chain = vt % NCHAINS;
    const unsigned tk = vt / NCHAINS;
    const unsigned b  = chain >> 1;
    const unsigned ch = chain & 1;
    const unsigned c  = ch * CGROUP + tid;
    const int t0 = tk * R_ROWS;

    if (tid < R_ROWS)
        s_inv[tid] = 1.0f / (float)(t0 + tid + 1);

    const size_t base = (size_t)b * T_DIM * C_DIM + (size_t)t0 * C_DIM + c;
    const float* __restrict__ xp = x + base;
    float* __restrict__ op = out + base;

    // Batched independent loads: 16 coalesced 128B lines in flight per warp.
    float v[R_ROWS];
    #pragma unroll
    for (int u = 0; u < R_ROWS; ++u)
        v[u] = __ldg(xp + (size_t)u * C_DIM);

    // Local inclusive scan in registers.
    #pragma unroll
    for (int u = 1; u < R_ROWS; ++u)
        v[u] += v[u - 1];

    __syncthreads();   // s_inv ready (off the inter-CTA critical tail)

    // Resolve prefix: per-thread spin on predecessor's packed word, then
    // consume-and-reset so the slot is zero for the next launch.
    float prefix = 0.0f;
    if (tk != 0) {
        unsigned long long* predp =
            &g_incl[(size_t)(vt - NCHAINS) * CGROUP + tid];
        unsigned long long pk;
        do { pk = *(volatile unsigned long long*)predp; }
        while ((pk >> 32) == 0ull);
        prefix = __uint_as_float((unsigned)(pk & 0xFFFFFFFFu));
        *(volatile unsigned long long*)predp = 0ull;   // consume-reset
    }

    // Publish own inclusive prefix — except the last chunk (no successor).
    if (tk != NTK - 1) {
        const float incl = prefix + v[R_ROWS - 1];
        unsigned long long pk = (1ull << 32)
                              | (unsigned long long)__float_as_uint(incl);
        atomicExch(&g_incl[(size_t)vt * CGROUP + tid], pk);
    }

    // Scaled output: (prefix + local inclusive) / (t+1). Streaming stores.
    #pragma unroll
    for (int u = 0; u < R_ROWS; ++u)
        __stcs(op + (size_t)u * C_DIM, (prefix + v[u]) * s_inv[u]);
}

extern "C" void kernel_launch(void* const* d_in, const int* in_sizes, int n_in,
                              void* d_out, int out_size) {
    const float* x = (const float*)d_in[0];
    float* out = (float*)d_out;
    (void)in_sizes; (void)n_in; (void)out_size;

    causal_bow_scan<<<NTILES, CGROUP>>>(x, out);
}

// round 8
// speedup vs baseline: 1.4028x; 1.4028x over previous
#include <cuda_runtime.h>
#include <cuda_bf16.h>

// Causal BoW = running mean along T. Shapes: B=32, T=2048, C=512, fp32.
//
// Single-pass CHAINED scan, SELF-CLEANING, BIG TILES:
//  tile = (chain, tk): chain = (b, c-half) -> 64 chains; tk = chunk of
//  R=64 rows -> 32 chunks/chain; 2048 tiles.
//  256-thread CTA = one thread per column, 64 rows in registers.
//  Rationale (R6 vs R7 evidence): bigger tiles amortize protocol overhead
//  and shorten the chain wavefront (32 steps ~ 8us serial depth). Latency
//  is hidden by MLP (64 independent 128B lines in flight per warp), not
//  occupancy.
//  Per-column inclusive prefixes published as ONE packed 64-bit word
//  (status<<32 | float bits) via atomicExch. Successor threads spin with
//  volatile 64-bit loads, then RESET the slot (consume-and-reset). Last
//  chunk never publishes; final ticket-holder resets the ticket. All
//  device state returns to zero after every launch: graph-safe, no allocs.

#define B_DIM 32
#define T_DIM 2048
#define C_DIM 512
#define R_ROWS 64
#define CGROUP 256
#define NCHAINS (B_DIM * (C_DIM / CGROUP))   // 64
#define NTK (T_DIM / R_ROWS)                 // 32
#define NTILES (NCHAINS * NTK)               // 2048

__device__ unsigned long long g_incl[(size_t)NTILES * CGROUP];  // 4 MB packed
__device__ unsigned int g_ticket;

__global__ __launch_bounds__(CGROUP)
void causal_bow_scan(const float* __restrict__ x, float* __restrict__ out) {
    __shared__ unsigned s_tile;
    __shared__ float s_inv[R_ROWS];

    const int tid = threadIdx.x;
    if (tid == 0) {
        unsigned t = atomicAdd(&g_ticket, 1u);
        s_tile = t;
        // Last ticket drawn -> all atomicAdds on g_ticket have serialized;
        // safe to reset for the next (graph-replayed) launch.
        if (t == NTILES - 1) atomicExch(&g_ticket, 0u);
    }
    __syncthreads();

    const unsigned vt = s_tile;
    const unsigned chain = vt % NCHAINS;
    const unsigned tk = vt / NCHAINS;
    const unsigned b  = chain >> 1;
    const unsigned ch = chain & 1;
    const unsigned c  = ch * CGROUP + tid;
    const int t0 = tk * R_ROWS;

    if (tid < R_ROWS)
        s_inv[tid] = 1.0f / (float)(t0 + tid + 1);

    const size_t base = (size_t)b * T_DIM * C_DIM + (size_t)t0 * C_DIM + c;
    const float* __restrict__ xp = x + base;
    float* __restrict__ op = out + base;

    // Batched independent loads: 64 coalesced 128B lines in flight per warp.
    float v[R_ROWS];
    #pragma unroll
    for (int u = 0; u < R_ROWS; ++u)
        v[u] = __ldg(xp + (size_t)u * C_DIM);

    // Local inclusive scan in registers.
    #pragma unroll
    for (int u = 1; u < R_ROWS; ++u)
        v[u] += v[u - 1];

    __syncthreads();   // s_inv ready (off the inter-CTA critical tail)

    // Resolve prefix: per-thread spin on predecessor's packed word, then
    // consume-and-reset so the slot is zero for the next launch.
    float prefix = 0.0f;
    if (tk != 0) {
        unsigned long long* predp =
            &g_incl[(size_t)(vt - NCHAINS) * CGROUP + tid];
        unsigned long long pk;
        do { pk = *(volatile unsigned long long*)predp; }
        while ((pk >> 32) == 0ull);
        prefix = __uint_as_float((unsigned)(pk & 0xFFFFFFFFu));
        *(volatile unsigned long long*)predp = 0ull;   // consume-reset
    }

    // Publish own inclusive prefix — except the last chunk (no successor).
    // Published BEFORE the 64 output stores so successors unblock early.
    if (tk != NTK - 1) {
        const float incl = prefix + v[R_ROWS - 1];
        unsigned long long pk = (1ull << 32)
                              | (unsigned long long)__float_as_uint(incl);
        atomicExch(&g_incl[(size_t)vt * CGROUP + tid], pk);
    }

    // Scaled output: (prefix + local inclusive) / (t+1). Streaming stores.
    #pragma unroll
    for (int u = 0; u < R_ROWS; ++u)
        __stcs(op + (size_t)u * C_DIM, (prefix + v[u]) * s_inv[u]);
}

extern "C" void kernel_launch(void* const* d_in, const int* in_sizes, int n_in,
                              void* d_out, int out_size) {
    const float* x = (const float*)d_in[0];
    float* out = (float*)d_out;
    (void)in_sizes; (void)n_in; (void)out_size;

    causal_bow_scan<<<NTILES, CGROUP>>>(x, out);
}

// round 10
// speedup vs baseline: 1.4231x; 1.0144x over previous
#include <cuda_runtime.h>
#include <cuda_bf16.h>

// Causal BoW = running mean along T. Shapes: B=32, T=2048, C=512, fp32.
//
// Single-pass CHAINED scan, SELF-CLEANING, BIG TILES, FINE CTAs:
//  tile = (chain, tk): chain = (b, c-quarter) -> 128 chains; tk = chunk of
//  R=64 rows -> 32 chunks/chain; 4096 tiles.
//  128-thread CTA = one thread per column, 64 rows in registers.
//  6 CTAs/SM -> finer overlap of load/spin/store phases than R8's 3x256.
//  Latency hidden by MLP (64 independent 128B lines in flight per warp).
//  Per-column inclusive prefixes published as ONE packed 64-bit word
//  (status<<32 | float bits) via atomicExch. Successor threads spin with
//  volatile 64-bit loads, then RESET the slot (consume-and-reset). Last
//  chunk never publishes; final ticket-holder resets the ticket. All
//  device state returns to zero after every launch: graph-safe, no allocs.

#define B_DIM 32
#define T_DIM 2048
#define C_DIM 512
#define R_ROWS 64
#define CGROUP 128
#define NCHAINS (B_DIM * (C_DIM / CGROUP))   // 128
#define NTK (T_DIM / R_ROWS)                 // 32
#define NTILES (NCHAINS * NTK)               // 4096

__device__ unsigned long long g_incl[(size_t)NTILES * CGROUP];  // 4 MB packed
__device__ unsigned int g_ticket;

__global__ __launch_bounds__(CGROUP, 6)
void causal_bow_scan(const float* __restrict__ x, float* __restrict__ out) {
    __shared__ unsigned s_tile;
    __shared__ float s_inv[R_ROWS];

    const int tid = threadIdx.x;
    if (tid == 0) {
        unsigned t = atomicAdd(&g_ticket, 1u);
        s_tile = t;
        // Last ticket drawn -> all atomicAdds on g_ticket have serialized;
        // safe to reset for the next (graph-replayed) launch.
        if (t == NTILES - 1) atomicExch(&g_ticket, 0u);
    }
    __syncthreads();

    const unsigned vt = s_tile;
    const unsigned chain = vt % NCHAINS;
    const unsigned tk = vt / NCHAINS;
    const unsigned b  = chain >> 2;            // chain / 4
    const unsigned cq = chain & 3;             // chain % 4
    const unsigned c  = cq * CGROUP + tid;
    const int t0 = tk * R_ROWS;

    if (tid < R_ROWS)
        s_inv[tid] = 1.0f / (float)(t0 + tid + 1);

    const size_t base = (size_t)b * T_DIM * C_DIM + (size_t)t0 * C_DIM + c;
    const float* __restrict__ xp = x + base;
    float* __restrict__ op = out + base;

    // Batched independent loads: 64 coalesced 128B lines in flight per warp.
    float v[R_ROWS];
    #pragma unroll
    for (int u = 0; u < R_ROWS; ++u)
        v[u] = __ldg(xp + (size_t)u * C_DIM);

    // Local inclusive scan in registers.
    #pragma unroll
    for (int u = 1; u < R_ROWS; ++u)
        v[u] += v[u - 1];

    // Resolve prefix: per-thread spin on predecessor's packed word, then
    // consume-and-reset so the slot is zero for the next launch.
    // (No barrier before this: spin/publish are per-warp independent.)
    float prefix = 0.0f;
    if (tk != 0) {
        unsigned long long* predp =
            &g_incl[(size_t)(vt - NCHAINS) * CGROUP + tid];
        unsigned long long pk;
        do { pk = *(volatile unsigned long long*)predp; }
        while ((pk >> 32) == 0ull);
        prefix = __uint_as_float((unsigned)(pk & 0xFFFFFFFFu));
        *(volatile unsigned long long*)predp = 0ull;   // consume-reset
    }

    // Publish own inclusive prefix — except the last chunk (no successor).
    // Published BEFORE the 64 output stores so successors unblock early.
    if (tk != NTK - 1) {
        const float incl = prefix + v[R_ROWS - 1];
        unsigned long long pk = (1ull << 32)
                              | (unsigned long long)__float_as_uint(incl);
        atomicExch(&g_incl[(size_t)vt * CGROUP + tid], pk);
    }

    __syncthreads();   // s_inv ready (only the store loop needs it)

    // Scaled output: (prefix + local inclusive) / (t+1). Streaming stores.
    #pragma unroll
    for (int u = 0; u < R_ROWS; ++u)
        __stcs(op + (size_t)u * C_DIM, (prefix + v[u]) * s_inv[u]);
}

extern "C" void kernel_launch(void* const* d_in, const int* in_sizes, int n_in,
                              void* d_out, int out_size) {
    const float* x = (const float*)d_in[0];
    float* out = (float*)d_out;
    (void)in_sizes; (void)n_in; (void)out_size;

    causal_bow_scan<<<NTILES, CGROUP>>>(x, out);
}